// round 16
// baseline (speedup 1.0000x reference)
#include <cuda_runtime.h>
#include <math.h>

#define NN 10000
#define EE 160000
#define ET (EE + NN)
#define EIN 16
#define HID 128
#define HEADS 4
#define AGB 888          // persistent agg grid: 6 blocks/SM x 148 SMs

typedef unsigned long long u64;

// ---------------- f32x2 helpers (GEMM only) ----------------
__device__ __forceinline__ u64 dupf(float v) {
    u64 r; unsigned u = __float_as_uint(v);
    asm("mov.b64 %0, {%1,%2};" : "=l"(r) : "r"(u), "r"(u));
    return r;
}
__device__ __forceinline__ void upk(u64 p, float& lo, float& hi) {
    unsigned a, b;
    asm("mov.b64 {%0,%1}, %2;" : "=r"(a), "=r"(b) : "l"(p));
    lo = __uint_as_float(a); hi = __uint_as_float(b);
}
__device__ __forceinline__ u64 fma2(u64 a, u64 b, u64 c) {
    u64 d; asm("fma.rn.f32x2 %0, %1, %2, %3;" : "=l"(d) : "l"(a), "l"(b), "l"(c));
    return d;
}

// ---------------- scratch (zero at module load; k_clean restores zeros) ----------------
__device__ float g_h[2][NN * HID];
__device__ float g_xlr[NN * 1024];
__device__ float g_asum[NN * EIN];
__device__ int   g_deg[NN];
__device__ int   g_cursor[NN];
__device__ int   g_rowptr[NN + 1];
__device__ __align__(8) int2 g_se[ET];               // (src, eid) CSR-ordered
__device__ __align__(16) float g_selfA[NN * EIN];    // self-loop mean attrs (16 floats/row)
__device__ __align__(16) float g_M[3 * 17 * 512];

// ---------------- launch 1: compose M + node emb + deg/attr sums ----------------
#define CB 204           // 204*128 = 26112 = 3*17*512
#define EB 625           // 625*16  = 10000
#define DB 1250          // 1250*128 = 160000 edges

__global__ void __launch_bounds__(128) k_pre(const float* __restrict__ x,
                                             const float* __restrict__ Wn,
                                             const float* __restrict__ bn,
                                             const float* __restrict__ edge_W,
                                             const float* __restrict__ edge_b,
                                             const float* __restrict__ We,
                                             const float* __restrict__ eattr,
                                             const int* __restrict__ eidx) {
    __shared__ float xs[16][64];
    int b = blockIdx.x, tid = threadIdx.x;
    if (b < CB) {
        int idx = b * 128 + tid;
        int l = idx / (17 * 512);
        int r = idx - l * (17 * 512);
        int k = r >> 9;
        int j = r & 511;
        const float* wp = We + l * 128 * 512 + j;
        float acc = 0.f;
#pragma unroll 8
        for (int t = 0; t < 128; t++) {
            float ev = (k < 16) ? edge_W[k * 128 + t] : edge_b[t];
            acc += ev * wp[t * 512];
        }
        g_M[idx] = acc;
        return;
    }
    if (b < CB + EB) {
        int nb = (b - CB) * 16;
#pragma unroll
        for (int i = 0; i < 8; i++) {
            int idx = tid + i * 128;
            int r = idx >> 6, c = idx & 63;
            xs[r][c] = x[(nb + r) * 64 + c];
        }
        __syncthreads();
        int c = tid;
        float acc[16];
#pragma unroll
        for (int n = 0; n < 16; n++) acc[n] = 0.f;
        for (int k = 0; k < 64; k++) {
            float wv = Wn[k * 128 + c];
#pragma unroll
            for (int n = 0; n < 16; n++) acc[n] += xs[n][k] * wv;
        }
        float bb = bn[c];
#pragma unroll
        for (int n = 0; n < 16; n++)
            g_h[0][(nb + n) * 128 + c] = acc[n] + bb;
        return;
    }
    int e = (b - CB - EB) * 128 + tid;       // < 160000 exact
    int d = eidx[EE + e];
    const float4* ap = (const float4*)(eattr + (size_t)e * 16);
    float* dst = g_asum + d * EIN;
#pragma unroll
    for (int q = 0; q < 4; q++) {
        float4 a = ap[q];
        atomicAdd(dst + q * 4 + 0, a.x);
        atomicAdd(dst + q * 4 + 1, a.y);
        atomicAdd(dst + q * 4 + 2, a.z);
        atomicAdd(dst + q * 4 + 3, a.w);
    }
    atomicAdd(&g_deg[d], 1);
}

// ---------------- launch 2: per-block scan + CSR scatter + selfA ----------------
__global__ void __launch_bounds__(256) k_scatscan(const int* __restrict__ eidx) {
    __shared__ int rp[NN + 1];
    __shared__ int part[256];
    int t = threadIdx.x;
    int base = t * 40;
    int run = 0;
    for (int i = 0; i < 40; i++) {
        int gi = base + i;
        int v = (gi < NN) ? (g_deg[gi] + 1) : 0;
        if (gi < NN) rp[gi] = run;
        run += v;
    }
    part[t] = run;
    __syncthreads();
    for (int off = 1; off < 256; off <<= 1) {
        int v = (t >= off) ? part[t - off] : 0;
        __syncthreads();
        part[t] += v;
        __syncthreads();
    }
    int offset = (t > 0) ? part[t - 1] : 0;
    for (int i = 0; i < 40; i++) {
        int gi = base + i;
        if (gi < NN) rp[gi] += offset;
    }
    if (t == 255) rp[NN] = part[255];
    __syncthreads();

    int i = blockIdx.x * 256 + t;
    if (i < ET) {
        int s, d;
        if (i < EE) { s = eidx[i]; d = eidx[EE + i]; }
        else        { s = i - EE;  d = s; }
        int pos  = atomicAdd(&g_cursor[d], 1);
        g_se[rp[d] + pos] = make_int2(s, i);
    }
    if (i < NN) {
        int dg = g_deg[i];
        float inv = 1.f / fmaxf((float)dg, 1.f);
#pragma unroll
        for (int k = 0; k < EIN; k++)
            g_selfA[i * EIN + k] = g_asum[i * EIN + k] * inv;
    }
    if (blockIdx.x == 0) {
        for (int j = t; j <= NN; j += 256) g_rowptr[j] = rp[j];
    }
}

// ---------------- cleanup: restore zero invariant for next replay ----------------
__global__ void k_clean() {
    int i = blockIdx.x * blockDim.x + threadIdx.x;
    if (i < NN * EIN) g_asum[i] = 0.f;
    if (i < NN) { g_deg[i] = 0; g_cursor[i] = 0; }
}

// ---------------- GEMM (benched 65.7us): g_xlr = h @ [Wl|Wr] + bias ----------------
#define GM 128
#define GN 64
#define GK 32

__global__ void __launch_bounds__(256) k_gemm2(int hinIdx,
                                               const float* __restrict__ WL, const float* __restrict__ bL,
                                               const float* __restrict__ WR, const float* __restrict__ bR) {
    __shared__ __align__(16) float Ast[GK][GM + 4];
    __shared__ __align__(16) float Bs[GK][GN];
    const float* H = g_h[hinIdx];
    int by = blockIdx.y;
    const float* W; const float* bias; int colOff;
    if (by < 8) { W = WL; bias = bL; colOff = 0; }
    else        { W = WR; bias = bR; colOff = 512; by -= 8; }
    int bm = blockIdx.x * GM, bn = by * GN;
    int tid = threadIdx.x;
    int tm = (tid >> 4) * 8;
    int tn = (tid & 15) * 4;

    u64 acc[4][4];
#pragma unroll
    for (int p = 0; p < 4; p++)
#pragma unroll
        for (int n = 0; n < 4; n++) acc[p][n] = 0ull;

    int lm = tid >> 3;
    int lk = (tid & 7) * 4;
    int brw = tid >> 4;
    int bc  = (tid & 15) * 4;

    for (int k0 = 0; k0 < 128; k0 += GK) {
#pragma unroll
        for (int i = 0; i < 4; i++) {
            int m = lm + i * 32;
            int gr = bm + m;
            float4 av = make_float4(0.f, 0.f, 0.f, 0.f);
            if (gr < NN) av = *(const float4*)(H + gr * 128 + k0 + lk);
            Ast[lk + 0][m] = av.x; Ast[lk + 1][m] = av.y;
            Ast[lk + 2][m] = av.z; Ast[lk + 3][m] = av.w;
        }
#pragma unroll
        for (int i = 0; i < 2; i++) {
            int r = brw + i * 16;
            *(float4*)&Bs[r][bc] = *(const float4*)(W + (k0 + r) * 512 + bn + bc);
        }
        __syncthreads();
#pragma unroll
        for (int kk = 0; kk < GK; kk++) {
            ulonglong2 p0 = *(const ulonglong2*)&Ast[kk][tm];
            ulonglong2 p1 = *(const ulonglong2*)&Ast[kk][tm + 4];
            u64 a0 = p0.x, a1 = p0.y, a2 = p1.x, a3 = p1.y;
            float4 b = *(const float4*)&Bs[kk][tn];
            u64 b0 = dupf(b.x), b1 = dupf(b.y), b2 = dupf(b.z), b3 = dupf(b.w);
            acc[0][0] = fma2(a0, b0, acc[0][0]); acc[0][1] = fma2(a0, b1, acc[0][1]);
            acc[0][2] = fma2(a0, b2, acc[0][2]); acc[0][3] = fma2(a0, b3, acc[0][3]);
            acc[1][0] = fma2(a1, b0, acc[1][0]); acc[1][1] = fma2(a1, b1, acc[1][1]);
            acc[1][2] = fma2(a1, b2, acc[1][2]); acc[1][3] = fma2(a1, b3, acc[1][3]);
            acc[2][0] = fma2(a2, b0, acc[2][0]); acc[2][1] = fma2(a2, b1, acc[2][1]);
            acc[2][2] = fma2(a2, b2, acc[2][2]); acc[2][3] = fma2(a2, b3, acc[2][3]);
            acc[3][0] = fma2(a3, b0, acc[3][0]); acc[3][1] = fma2(a3, b1, acc[3][1]);
            acc[3][2] = fma2(a3, b2, acc[3][2]); acc[3][3] = fma2(a3, b3, acc[3][3]);
        }
        __syncthreads();
    }

    float4 bv = *(const float4*)(bias + bn + tn);
#pragma unroll
    for (int p = 0; p < 4; p++) {
        float c0[4], c1[4];
#pragma unroll
        for (int n = 0; n < 4; n++) upk(acc[p][n], c0[n], c1[n]);
        int r0 = bm + tm + 2 * p, r1 = r0 + 1;
        if (r0 < NN) {
            float4 o = make_float4(c0[0] + bv.x, c0[1] + bv.y, c0[2] + bv.z, c0[3] + bv.w);
            *(float4*)(g_xlr + (size_t)r0 * 1024 + colOff + bn + tn) = o;
        }
        if (r1 < NN) {
            float4 o = make_float4(c1[0] + bv.x, c1[1] + bv.y, c1[2] + bv.z, c1[3] + bv.w);
            *(float4*)(g_xlr + (size_t)r1 * 1024 + colOff + bn + tn) = o;
        }
    }
}

// ---------------- GATv2 aggregation: persistent, M16 folded into xr, 6 blocks/SM ----------------
// c16 is node-uniform (deg>0 => every incident edge incl. self-loop has bias coeff 1;
// deg==0 => single self-loop with ALL coeffs 0). So c16*M[16] moves to the per-node
// prologue: xrv += M16 iff deg>0. Real-edge coefficients are then raw eattr rows.
__global__ void __launch_bounds__(128, 6) k_agg(const float* __restrict__ att_l,
                                                const float* __restrict__ bias_l,
                                                const float* __restrict__ eattr,
                                                int lM, float* __restrict__ outp, int outSel) {
    int t = threadIdx.x;
    int w = t >> 5, lam = t & 31;            // warp = head
    int jbase = w * HID + lam * 4;

    const float* Ml = g_M + lM * (17 * 512);
    float4 Mreg[16];
#pragma unroll
    for (int k = 0; k < 16; k++) Mreg[k] = *(const float4*)(Ml + k * 512 + jbase);
    float4 M16r = *(const float4*)(Ml + 16 * 512 + jbase);
    float4 attv = *(const float4*)(att_l + jbase);
    float biasv = bias_l[t];

    __shared__ float sred[HEADS][HID];
    float* dstbuf = outp ? outp : g_h[outSel];

    for (int v = blockIdx.x; v < NN; v += AGB) {
        int beg = g_rowptr[v], end = g_rowptr[v + 1];
        float4 xrv = *(const float4*)(g_xlr + (size_t)v * 1024 + 512 + jbase);
        if (end - beg > 1) {                  // deg>0: fold bias column into xr
            xrv.x += M16r.x; xrv.y += M16r.y; xrv.z += M16r.z; xrv.w += M16r.w;
        }
        float acc0 = 0.f, acc1 = 0.f, acc2 = 0.f, acc3 = 0.f;
        float denom = 0.f;

#pragma unroll 2
        for (int i = beg; i < end; i++) {
            int2 se = g_se[i];                // warp-uniform broadcast
            int eid = se.y;
            const float4* p4 = (eid < EE)
                ? (const float4*)(eattr + (size_t)eid * 16)
                : (const float4*)(g_selfA + (size_t)(eid - EE) * EIN);
            float4 a0 = p4[0], a1 = p4[1], a2 = p4[2], a3 = p4[3];
            float4 xl = *(const float4*)(g_xlr + (size_t)se.x * 1024 + jbase);

            // two independent FMA chains per channel for ILP
            float m0a = xrv.x + xl.x, m1a = xrv.y + xl.y;
            float m2a = xrv.z + xl.z, m3a = xrv.w + xl.w;
            float m0b = a0.x * Mreg[0].x,  m1b = a0.x * Mreg[0].y;
            float m2b = a0.x * Mreg[0].z,  m3b = a0.x * Mreg[0].w;
            m0a += a0.y * Mreg[1].x;  m1a += a0.y * Mreg[1].y;  m2a += a0.y * Mreg[1].z;  m3a += a0.y * Mreg[1].w;
            m0b += a0.z * Mreg[2].x;  m1b += a0.z * Mreg[2].y;  m2b += a0.z * Mreg[2].z;  m3b += a0.z * Mreg[2].w;
            m0a += a0.w * Mreg[3].x;  m1a += a0.w * Mreg[3].y;  m2a += a0.w * Mreg[3].z;  m3a += a0.w * Mreg[3].w;
            m0b += a1.x * Mreg[4].x;  m1b += a1.x * Mreg[4].y;  m2b += a1.x * Mreg[4].z;  m3b += a1.x * Mreg[4].w;
            m0a += a1.y * Mreg[5].x;  m1a += a1.y * Mreg[5].y;  m2a += a1.y * Mreg[5].z;  m3a += a1.y * Mreg[5].w;
            m0b += a1.z * Mreg[6].x;  m1b += a1.z * Mreg[6].y;  m2b += a1.z * Mreg[6].z;  m3b += a1.z * Mreg[6].w;
            m0a += a1.w * Mreg[7].x;  m1a += a1.w * Mreg[7].y;  m2a += a1.w * Mreg[7].z;  m3a += a1.w * Mreg[7].w;
            m0b += a2.x * Mreg[8].x;  m1b += a2.x * Mreg[8].y;  m2b += a2.x * Mreg[8].z;  m3b += a2.x * Mreg[8].w;
            m0a += a2.y * Mreg[9].x;  m1a += a2.y * Mreg[9].y;  m2a += a2.y * Mreg[9].z;  m3a += a2.y * Mreg[9].w;
            m0b += a2.z * Mreg[10].x; m1b += a2.z * Mreg[10].y; m2b += a2.z * Mreg[10].z; m3b += a2.z * Mreg[10].w;
            m0a += a2.w * Mreg[11].x; m1a += a2.w * Mreg[11].y; m2a += a2.w * Mreg[11].z; m3a += a2.w * Mreg[11].w;
            m0b += a3.x * Mreg[12].x; m1b += a3.x * Mreg[12].y; m2b += a3.x * Mreg[12].z; m3b += a3.x * Mreg[12].w;
            m0a += a3.y * Mreg[13].x; m1a += a3.y * Mreg[13].y; m2a += a3.y * Mreg[13].z; m3a += a3.y * Mreg[13].w;
            m0b += a3.z * Mreg[14].x; m1b += a3.z * Mreg[14].y; m2b += a3.z * Mreg[14].z; m3b += a3.z * Mreg[14].w;
            m0a += a3.w * Mreg[15].x; m1a += a3.w * Mreg[15].y; m2a += a3.w * Mreg[15].z; m3a += a3.w * Mreg[15].w;
            float m0 = m0a + m0b, m1 = m1a + m1b, m2 = m2a + m2b, m3 = m3a + m3b;
            // leaky(x) = 0.6x + 0.4|x|
            m0 = 0.6f * m0 + 0.4f * fabsf(m0);
            m1 = 0.6f * m1 + 0.4f * fabsf(m1);
            m2 = 0.6f * m2 + 0.4f * fabsf(m2);
            m3 = 0.6f * m3 + 0.4f * fabsf(m3);
            float part = m0 * attv.x + m1 * attv.y + m2 * attv.z + m3 * attv.w;
#pragma unroll
            for (int o = 16; o; o >>= 1)
                part += __shfl_xor_sync(0xffffffffu, part, o);

            float p = __expf(part);           // no max subtraction: logits are O(1)
            denom += p;
            acc0 += p * xl.x; acc1 += p * xl.y;
            acc2 += p * xl.z; acc3 += p * xl.w;
        }

        __syncthreads();                      // prior node's sred reads complete
        float inv = 1.f / denom;
        sred[w][lam * 4 + 0] = acc0 * inv;
        sred[w][lam * 4 + 1] = acc1 * inv;
        sred[w][lam * 4 + 2] = acc2 * inv;
        sred[w][lam * 4 + 3] = acc3 * inv;
        __syncthreads();
        float o = (sred[0][t] + sred[1][t] + sred[2][t] + sred[3][t]) * 0.25f + biasv;
        dstbuf[(size_t)v * HID + t] = fmaxf(o, 0.f);
    }
}

// ---------------- launch ----------------
extern "C" void kernel_launch(void* const* d_in, const int* in_sizes, int n_in,
                              void* d_out, int out_size) {
    const float* x       = (const float*)d_in[0];
    const int*   eidx    = (const int*)  d_in[1];
    const float* eattr   = (const float*)d_in[2];
    const float* node_W  = (const float*)d_in[3];
    const float* node_b  = (const float*)d_in[4];
    const float* edge_W  = (const float*)d_in[5];
    const float* edge_b  = (const float*)d_in[6];
    const float* Wl      = (const float*)d_in[7];
    const float* bl      = (const float*)d_in[8];
    const float* Wr      = (const float*)d_in[9];
    const float* br      = (const float*)d_in[10];
    const float* We      = (const float*)d_in[11];
    const float* att     = (const float*)d_in[12];
    const float* bias    = (const float*)d_in[13];
    float* out = (float*)d_out;

    dim3 gdim((NN + GM - 1) / GM, 16);

    k_pre<<<CB + EB + DB, 128>>>(x, node_W, node_b, edge_W, edge_b, We, eattr, eidx); // 1
    k_scatscan<<<(ET + 255) / 256, 256>>>(eidx);                                       // 2
    k_gemm2<<<gdim, 256>>>(0, Wl, bl, Wr, br);                                         // 3
    k_agg<<<AGB, 128>>>(att, bias, eattr, 0, (float*)nullptr, 1);                      // 4  <- ncu target
    k_gemm2<<<gdim, 256>>>(1, Wl + (size_t)1 * 128 * 512, bl + 512,                    // 5
                           Wr + (size_t)1 * 128 * 512, br + 512);
    k_agg<<<AGB, 128>>>(att + HEADS * HID, bias + HID, eattr, 1, (float*)nullptr, 0);  // 6
    k_gemm2<<<gdim, 256>>>(0, Wl + (size_t)2 * 128 * 512, bl + 1024,                   // 7
                           Wr + (size_t)2 * 128 * 512, br + 1024);
    k_agg<<<AGB, 128>>>(att + 2 * HEADS * HID, bias + 2 * HID, eattr, 2, out, 0);      // 8
    k_clean<<<(NN * EIN + 255) / 256, 256>>>();                                        // 9
}

// round 17
// speedup vs baseline: 1.1719x; 1.1719x over previous
#include <cuda_runtime.h>
#include <math.h>

#define NN 10000
#define EE 160000
#define ET (EE + NN)
#define EIN 16
#define HID 128
#define HEADS 4
#define AGB 740          // persistent agg grid: 5 blocks/SM x 148 SMs

typedef unsigned long long u64;

// ---------------- f32x2 helpers (GEMM only) ----------------
__device__ __forceinline__ u64 dupf(float v) {
    u64 r; unsigned u = __float_as_uint(v);
    asm("mov.b64 %0, {%1,%2};" : "=l"(r) : "r"(u), "r"(u));
    return r;
}
__device__ __forceinline__ void upk(u64 p, float& lo, float& hi) {
    unsigned a, b;
    asm("mov.b64 {%0,%1}, %2;" : "=r"(a), "=r"(b) : "l"(p));
    lo = __uint_as_float(a); hi = __uint_as_float(b);
}
__device__ __forceinline__ u64 fma2(u64 a, u64 b, u64 c) {
    u64 d; asm("fma.rn.f32x2 %0, %1, %2, %3;" : "=l"(d) : "l"(a), "l"(b), "l"(c));
    return d;
}

// ---------------- scratch (zero at module load; k_clean restores zeros) ----------------
__device__ float g_h[2][NN * HID];
__device__ float g_xlr[NN * 1024];
__device__ float g_asum[NN * EIN];
__device__ int   g_deg[NN];
__device__ int   g_cursor[NN];
__device__ int   g_rowptr[NN + 1];
__device__ __align__(8) int2 g_se[ET];               // (src, eid) CSR-ordered
__device__ __align__(16) float g_eaPad[(size_t)ET * 20];  // eid-indexed: 16 attrs + c16 + pad3
__device__ __align__(16) float g_M[3 * 17 * 512];

// ---------------- launch 1: compose M + node emb + deg/attr sums + eaPad(real edges) ----------------
#define CB 204           // 204*128 = 26112 = 3*17*512
#define EB 625           // 625*16  = 10000
#define DB 1250          // 1250*128 = 160000 edges
#define PB 6250          // 6250*128 = 800000 = EE*5 float4 rows of eaPad

__global__ void __launch_bounds__(128) k_pre(const float* __restrict__ x,
                                             const float* __restrict__ Wn,
                                             const float* __restrict__ bn,
                                             const float* __restrict__ edge_W,
                                             const float* __restrict__ edge_b,
                                             const float* __restrict__ We,
                                             const float* __restrict__ eattr,
                                             const int* __restrict__ eidx) {
    __shared__ float xs[16][64];
    int b = blockIdx.x, tid = threadIdx.x;
    if (b < CB) {
        int idx = b * 128 + tid;
        int l = idx / (17 * 512);
        int r = idx - l * (17 * 512);
        int k = r >> 9;
        int j = r & 511;
        const float* wp = We + l * 128 * 512 + j;
        float acc = 0.f;
#pragma unroll 8
        for (int t = 0; t < 128; t++) {
            float ev = (k < 16) ? edge_W[k * 128 + t] : edge_b[t];
            acc += ev * wp[t * 512];
        }
        g_M[idx] = acc;
        return;
    }
    if (b < CB + EB) {
        int nb = (b - CB) * 16;
#pragma unroll
        for (int i = 0; i < 8; i++) {
            int idx = tid + i * 128;
            int r = idx >> 6, c = idx & 63;
            xs[r][c] = x[(nb + r) * 64 + c];
        }
        __syncthreads();
        int c = tid;
        float acc[16];
#pragma unroll
        for (int n = 0; n < 16; n++) acc[n] = 0.f;
        for (int k = 0; k < 64; k++) {
            float wv = Wn[k * 128 + c];
#pragma unroll
            for (int n = 0; n < 16; n++) acc[n] += xs[n][k] * wv;
        }
        float bb = bn[c];
#pragma unroll
        for (int n = 0; n < 16; n++)
            g_h[0][(nb + n) * 128 + c] = acc[n] + bb;
        return;
    }
    if (b < CB + EB + DB) {
        int e = (b - CB - EB) * 128 + tid;       // < 160000 exact
        int d = eidx[EE + e];
        const float4* ap = (const float4*)(eattr + (size_t)e * 16);
        float* dst = g_asum + d * EIN;
#pragma unroll
        for (int q = 0; q < 4; q++) {
            float4 a = ap[q];
            atomicAdd(dst + q * 4 + 0, a.x);
            atomicAdd(dst + q * 4 + 1, a.y);
            atomicAdd(dst + q * 4 + 2, a.z);
            atomicAdd(dst + q * 4 + 3, a.w);
        }
        atomicAdd(&g_deg[d], 1);
        return;
    }
    // eaPad for real edges: row e = [eattr(16) | 1 | 0 0 0]
    int idx = (b - CB - EB - DB) * 128 + tid;    // < 800000 exact (float4 units)
    int e = idx / 5, q = idx - e * 5;
    float4 val;
    if (q < 4) val = *(const float4*)(eattr + (size_t)e * 16 + q * 4);
    else       val = make_float4(1.f, 0.f, 0.f, 0.f);
    ((float4*)g_eaPad)[idx] = val;
}

// ---------------- launch 2: per-block scan + CSR scatter + eaPad(self rows) ----------------
__global__ void __launch_bounds__(256) k_scatscan(const int* __restrict__ eidx) {
    __shared__ int rp[NN + 1];
    __shared__ int part[256];
    int t = threadIdx.x;
    int base = t * 40;
    int run = 0;
    for (int i = 0; i < 40; i++) {
        int gi = base + i;
        int v = (gi < NN) ? (g_deg[gi] + 1) : 0;
        if (gi < NN) rp[gi] = run;
        run += v;
    }
    part[t] = run;
    __syncthreads();
    for (int off = 1; off < 256; off <<= 1) {
        int v = (t >= off) ? part[t - off] : 0;
        __syncthreads();
        part[t] += v;
        __syncthreads();
    }
    int offset = (t > 0) ? part[t - 1] : 0;
    for (int i = 0; i < 40; i++) {
        int gi = base + i;
        if (gi < NN) rp[gi] += offset;
    }
    if (t == 255) rp[NN] = part[255];
    __syncthreads();

    int i = blockIdx.x * 256 + t;
    if (i < ET) {
        int s, d;
        if (i < EE) { s = eidx[i]; d = eidx[EE + i]; }
        else        { s = i - EE;  d = s; }
        int pos  = atomicAdd(&g_cursor[d], 1);
        g_se[rp[d] + pos] = make_int2(s, i);
    }
    if (i < NN) {
        int dg = g_deg[i];
        float inv = 1.f / fmaxf((float)dg, 1.f);
        float* dst = g_eaPad + (size_t)(EE + i) * 20;
#pragma unroll
        for (int k = 0; k < EIN; k++)
            dst[k] = g_asum[i * EIN + k] * inv;
        dst[16] = (dg > 0) ? 1.f : 0.f;
        dst[17] = 0.f; dst[18] = 0.f; dst[19] = 0.f;
    }
    if (blockIdx.x == 0) {
        for (int j = t; j <= NN; j += 256) g_rowptr[j] = rp[j];
    }
}

// ---------------- cleanup: restore zero invariant for next replay ----------------
__global__ void k_clean() {
    int i = blockIdx.x * blockDim.x + threadIdx.x;
    if (i < NN * EIN) g_asum[i] = 0.f;
    if (i < NN) { g_deg[i] = 0; g_cursor[i] = 0; }
}

// ---------------- GEMM (benched 65.7us): g_xlr = h @ [Wl|Wr] + bias ----------------
#define GM 128
#define GN 64
#define GK 32

__global__ void __launch_bounds__(256) k_gemm2(int hinIdx,
                                               const float* __restrict__ WL, const float* __restrict__ bL,
                                               const float* __restrict__ WR, const float* __restrict__ bR) {
    __shared__ __align__(16) float Ast[GK][GM + 4];
    __shared__ __align__(16) float Bs[GK][GN];
    const float* H = g_h[hinIdx];
    int by = blockIdx.y;
    const float* W; const float* bias; int colOff;
    if (by < 8) { W = WL; bias = bL; colOff = 0; }
    else        { W = WR; bias = bR; colOff = 512; by -= 8; }
    int bm = blockIdx.x * GM, bn = by * GN;
    int tid = threadIdx.x;
    int tm = (tid >> 4) * 8;
    int tn = (tid & 15) * 4;

    u64 acc[4][4];
#pragma unroll
    for (int p = 0; p < 4; p++)
#pragma unroll
        for (int n = 0; n < 4; n++) acc[p][n] = 0ull;

    int lm = tid >> 3;
    int lk = (tid & 7) * 4;
    int brw = tid >> 4;
    int bc  = (tid & 15) * 4;

    for (int k0 = 0; k0 < 128; k0 += GK) {
#pragma unroll
        for (int i = 0; i < 4; i++) {
            int m = lm + i * 32;
            int gr = bm + m;
            float4 av = make_float4(0.f, 0.f, 0.f, 0.f);
            if (gr < NN) av = *(const float4*)(H + gr * 128 + k0 + lk);
            Ast[lk + 0][m] = av.x; Ast[lk + 1][m] = av.y;
            Ast[lk + 2][m] = av.z; Ast[lk + 3][m] = av.w;
        }
#pragma unroll
        for (int i = 0; i < 2; i++) {
            int r = brw + i * 16;
            *(float4*)&Bs[r][bc] = *(const float4*)(W + (k0 + r) * 512 + bn + bc);
        }
        __syncthreads();
#pragma unroll
        for (int kk = 0; kk < GK; kk++) {
            ulonglong2 p0 = *(const ulonglong2*)&Ast[kk][tm];
            ulonglong2 p1 = *(const ulonglong2*)&Ast[kk][tm + 4];
            u64 a0 = p0.x, a1 = p0.y, a2 = p1.x, a3 = p1.y;
            float4 b = *(const float4*)&Bs[kk][tn];
            u64 b0 = dupf(b.x), b1 = dupf(b.y), b2 = dupf(b.z), b3 = dupf(b.w);
            acc[0][0] = fma2(a0, b0, acc[0][0]); acc[0][1] = fma2(a0, b1, acc[0][1]);
            acc[0][2] = fma2(a0, b2, acc[0][2]); acc[0][3] = fma2(a0, b3, acc[0][3]);
            acc[1][0] = fma2(a1, b0, acc[1][0]); acc[1][1] = fma2(a1, b1, acc[1][1]);
            acc[1][2] = fma2(a1, b2, acc[1][2]); acc[1][3] = fma2(a1, b3, acc[1][3]);
            acc[2][0] = fma2(a2, b0, acc[2][0]); acc[2][1] = fma2(a2, b1, acc[2][1]);
            acc[2][2] = fma2(a2, b2, acc[2][2]); acc[2][3] = fma2(a2, b3, acc[2][3]);
            acc[3][0] = fma2(a3, b0, acc[3][0]); acc[3][1] = fma2(a3, b1, acc[3][1]);
            acc[3][2] = fma2(a3, b2, acc[3][2]); acc[3][3] = fma2(a3, b3, acc[3][3]);
        }
        __syncthreads();
    }

    float4 bv = *(const float4*)(bias + bn + tn);
#pragma unroll
    for (int p = 0; p < 4; p++) {
        float c0[4], c1[4];
#pragma unroll
        for (int n = 0; n < 4; n++) upk(acc[p][n], c0[n], c1[n]);
        int r0 = bm + tm + 2 * p, r1 = r0 + 1;
        if (r0 < NN) {
            float4 o = make_float4(c0[0] + bv.x, c0[1] + bv.y, c0[2] + bv.z, c0[3] + bv.w);
            *(float4*)(g_xlr + (size_t)r0 * 1024 + colOff + bn + tn) = o;
        }
        if (r1 < NN) {
            float4 o = make_float4(c1[0] + bv.x, c1[1] + bv.y, c1[2] + bv.z, c1[3] + bv.w);
            *(float4*)(g_xlr + (size_t)r1 * 1024 + colOff + bn + tn) = o;
        }
    }
}

// ---------------- GATv2 aggregation: persistent + smem-staged edge coefficients ----------------
// R15 math exactly (single-pass no-max, 17-col M, eaPad). New: per 32-edge chunk, the
// block cooperatively stages the 32 eaPad rows + se pairs into smem ONCE (coefficients
// were previously broadcast-loaded redundantly by all 4 warps -> ~20 wf/edge; now ~5).
__global__ void __launch_bounds__(128, 5) k_agg(const float* __restrict__ att_l,
                                                const float* __restrict__ bias_l,
                                                int lM, float* __restrict__ outp, int outSel) {
    int t = threadIdx.x;
    int w = t >> 5, lam = t & 31;            // warp = head
    int jbase = w * HID + lam * 4;

    const float* Ml = g_M + lM * (17 * 512);
    float4 Mreg[17];
#pragma unroll
    for (int k = 0; k < 17; k++) Mreg[k] = *(const float4*)(Ml + k * 512 + jbase);
    float4 attv = *(const float4*)(att_l + jbase);
    float biasv = bias_l[t];

    __shared__ __align__(16) float4 sEA[32][5];   // staged coefficient rows
    __shared__ int sS[32];                        // staged src ids
    __shared__ float sred[HEADS][HID];
    float* dstbuf = outp ? outp : g_h[outSel];

    for (int v = blockIdx.x; v < NN; v += AGB) {
        float4 xrv = *(const float4*)(g_xlr + (size_t)v * 1024 + 512 + jbase);
        float acc0 = 0.f, acc1 = 0.f, acc2 = 0.f, acc3 = 0.f;
        float denom = 0.f;

        int beg = g_rowptr[v], end = g_rowptr[v + 1];
        for (int c0 = beg; c0 < end; c0 += 32) {
            int cnt = min(32, end - c0);
            __syncthreads();                      // protect smem from prior chunk/node
            // cooperative stage: 5 float4 per edge, gathered once per block
            for (int idx = t; idx < cnt * 5; idx += 128) {
                int e = idx / 5, q = idx - e * 5;
                int eid = g_se[c0 + e].y;
                sEA[e][q] = *(const float4*)(g_eaPad + (size_t)eid * 20 + q * 4);
            }
            if (t < cnt) sS[t] = g_se[c0 + t].x;
            __syncthreads();

#pragma unroll 2
            for (int i = 0; i < cnt; i++) {
                int s = sS[i];
                float4 a0 = sEA[i][0], a1 = sEA[i][1], a2 = sEA[i][2], a3 = sEA[i][3];
                float c16 = sEA[i][4].x;
                float4 xl = *(const float4*)(g_xlr + (size_t)s * 1024 + jbase);

                float m0a = xrv.x + xl.x, m1a = xrv.y + xl.y;
                float m2a = xrv.z + xl.z, m3a = xrv.w + xl.w;
                float m0b = c16 * Mreg[16].x, m1b = c16 * Mreg[16].y;
                float m2b = c16 * Mreg[16].z, m3b = c16 * Mreg[16].w;
                m0a += a0.x * Mreg[0].x;  m1a += a0.x * Mreg[0].y;  m2a += a0.x * Mreg[0].z;  m3a += a0.x * Mreg[0].w;
                m0b += a0.y * Mreg[1].x;  m1b += a0.y * Mreg[1].y;  m2b += a0.y * Mreg[1].z;  m3b += a0.y * Mreg[1].w;
                m0a += a0.z * Mreg[2].x;  m1a += a0.z * Mreg[2].y;  m2a += a0.z * Mreg[2].z;  m3a += a0.z * Mreg[2].w;
                m0b += a0.w * Mreg[3].x;  m1b += a0.w * Mreg[3].y;  m2b += a0.w * Mreg[3].z;  m3b += a0.w * Mreg[3].w;
                m0a += a1.x * Mreg[4].x;  m1a += a1.x * Mreg[4].y;  m2a += a1.x * Mreg[4].z;  m3a += a1.x * Mreg[4].w;
                m0b += a1.y * Mreg[5].x;  m1b += a1.y * Mreg[5].y;  m2b += a1.y * Mreg[5].z;  m3b += a1.y * Mreg[5].w;
                m0a += a1.z * Mreg[6].x;  m1a += a1.z * Mreg[6].y;  m2a += a1.z * Mreg[6].z;  m3a += a1.z * Mreg[6].w;
                m0b += a1.w * Mreg[7].x;  m1b += a1.w * Mreg[7].y;  m2b += a1.w * Mreg[7].z;  m3b += a1.w * Mreg[7].w;
                m0a += a2.x * Mreg[8].x;  m1a += a2.x * Mreg[8].y;  m2a += a2.x * Mreg[8].z;  m3a += a2.x * Mreg[8].w;
                m0b += a2.y * Mreg[9].x;  m1b += a2.y * Mreg[9].y;  m2b += a2.y * Mreg[9].z;  m3b += a2.y * Mreg[9].w;
                m0a += a2.z * Mreg[10].x; m1a += a2.z * Mreg[10].y; m2a += a2.z * Mreg[10].z; m3a += a2.z * Mreg[10].w;
                m0b += a2.w * Mreg[11].x; m1b += a2.w * Mreg[11].y; m2b += a2.w * Mreg[11].z; m3b += a2.w * Mreg[11].w;
                m0a += a3.x * Mreg[12].x; m1a += a3.x * Mreg[12].y; m2a += a3.x * Mreg[12].z; m3a += a3.x * Mreg[12].w;
                m0b += a3.y * Mreg[13].x; m1b += a3.y * Mreg[13].y; m2b += a3.y * Mreg[13].z; m3b += a3.y * Mreg[13].w;
                m0a += a3.z * Mreg[14].x; m1a += a3.z * Mreg[14].y; m2a += a3.z * Mreg[14].z; m3a += a3.z * Mreg[14].w;
                m0b += a3.w * Mreg[15].x; m1b += a3.w * Mreg[15].y; m2b += a3.w * Mreg[15].z; m3b += a3.w * Mreg[15].w;
                float m0 = m0a + m0b, m1 = m1a + m1b, m2 = m2a + m2b, m3 = m3a + m3b;
                // leaky(x) = 0.6x + 0.4|x|
                m0 = 0.6f * m0 + 0.4f * fabsf(m0);
                m1 = 0.6f * m1 + 0.4f * fabsf(m1);
                m2 = 0.6f * m2 + 0.4f * fabsf(m2);
                m3 = 0.6f * m3 + 0.4f * fabsf(m3);
                float part = m0 * attv.x + m1 * attv.y + m2 * attv.z + m3 * attv.w;
#pragma unroll
                for (int o = 16; o; o >>= 1)
                    part += __shfl_xor_sync(0xffffffffu, part, o);

                float p = __expf(part);           // no max subtraction: logits are O(1)
                denom += p;
                acc0 += p * xl.x; acc1 += p * xl.y;
                acc2 += p * xl.z; acc3 += p * xl.w;
            }
        }

        __syncthreads();
        float inv = 1.f / denom;
        sred[w][lam * 4 + 0] = acc0 * inv;
        sred[w][lam * 4 + 1] = acc1 * inv;
        sred[w][lam * 4 + 2] = acc2 * inv;
        sred[w][lam * 4 + 3] = acc3 * inv;
        __syncthreads();
        float o = (sred[0][t] + sred[1][t] + sred[2][t] + sred[3][t]) * 0.25f + biasv;
        dstbuf[(size_t)v * HID + t] = fmaxf(o, 0.f);
    }
}

// ---------------- launch ----------------
extern "C" void kernel_launch(void* const* d_in, const int* in_sizes, int n_in,
                              void* d_out, int out_size) {
    const float* x       = (const float*)d_in[0];
    const int*   eidx    = (const int*)  d_in[1];
    const float* eattr   = (const float*)d_in[2];
    const float* node_W  = (const float*)d_in[3];
    const float* node_b  = (const float*)d_in[4];
    const float* edge_W  = (const float*)d_in[5];
    const float* edge_b  = (const float*)d_in[6];
    const float* Wl      = (const float*)d_in[7];
    const float* bl      = (const float*)d_in[8];
    const float* Wr      = (const float*)d_in[9];
    const float* br      = (const float*)d_in[10];
    const float* We      = (const float*)d_in[11];
    const float* att     = (const float*)d_in[12];
    const float* bias    = (const float*)d_in[13];
    float* out = (float*)d_out;

    dim3 gdim((NN + GM - 1) / GM, 16);

    k_pre<<<CB + EB + DB + PB, 128>>>(x, node_W, node_b, edge_W, edge_b, We, eattr, eidx); // 1
    k_scatscan<<<(ET + 255) / 256, 256>>>(eidx);                                            // 2
    k_gemm2<<<gdim, 256>>>(0, Wl, bl, Wr, br);                                              // 3
    k_agg<<<AGB, 128>>>(att, bias, 0, (float*)nullptr, 1);                                  // 4  <- ncu target
    k_gemm2<<<gdim, 256>>>(1, Wl + (size_t)1 * 128 * 512, bl + 512,                         // 5
                           Wr + (size_t)1 * 128 * 512, br + 512);
    k_agg<<<AGB, 128>>>(att + HEADS * HID, bias + HID, 1, (float*)nullptr, 0);              // 6
    k_gemm2<<<gdim, 256>>>(0, Wl + (size_t)2 * 128 * 512, bl + 1024,                        // 7
                           Wr + (size_t)2 * 128 * 512, br + 1024);
    k_agg<<<AGB, 128>>>(att + 2 * HEADS * HID, bias + 2 * HID, 2, out, 0);                  // 8
    k_clean<<<(NN * EIN + 255) / 256, 256>>>();                                             // 9
}